// round 5
// baseline (speedup 1.0000x reference)
#include <cuda_runtime.h>

#define K1 129
#define K2 257
#define K3 385
#define WOFF1 0
#define WOFF2 (K1*64)          // 8256
#define WOFF3 ((K1+K2)*64)     // 24704
#define WTOT  ((K1+K2+K3)*64)  // 49344
#define OFF_A  WTOT            // [385][16]
#define OFF_G  (OFF_A + 385*16)
#define OFF_BS (OFF_G + 64*16)
#define OFF_WL (OFF_BS + 192)
#define SMEM_FLOATS (OFF_WL + 386)
#define SMEM_BYTES  (SMEM_FLOATS*4)

__device__ __forceinline__ void cluster_sync_() {
    asm volatile("barrier.cluster.arrive.aligned;" ::: "memory");
    asm volatile("barrier.cluster.wait.aligned;" ::: "memory");
}
__device__ __forceinline__ void stc(unsigned a, unsigned r, float v) {
    unsigned ra;
    asm volatile("mapa.shared::cluster.u32 %0, %1, %2;" : "=r"(ra) : "r"(a), "r"(r));
    asm volatile("st.shared::cluster.f32 [%0], %1;" :: "r"(ra), "f"(v) : "memory");
}
__device__ __forceinline__ float sigf(float v) { return __fdividef(1.f, 1.f + __expf(-v)); }
__device__ __forceinline__ float thf(float v)  { return 1.f - __fdividef(2.f, 1.f + __expf(2.f*v)); }

__device__ __forceinline__ void matvec(const float* __restrict__ Wl, int K,
                                       const float* __restrict__ A, float* __restrict__ G,
                                       int l, int bq) {
    float a0=0.f, a1=0.f, a2=0.f, a3=0.f;
    #pragma unroll 4
    for (int k = 0; k < K; k++) {
        float w = Wl[k*64 + l];
        float4 a = *(const float4*)(A + k*16 + 4*bq);
        a0 += w*a.x; a1 += w*a.y; a2 += w*a.z; a3 += w*a.w;
    }
    *(float4*)(G + l*16 + 4*bq) = make_float4(a0, a1, a2, a3);
}

__global__ void __launch_bounds__(256, 1) __cluster_dims__(8, 1, 1)
lstm_k(const float* __restrict__ x,
       const float* __restrict__ Wih1, const float* __restrict__ Whh1,
       const float* __restrict__ bih1, const float* __restrict__ bhh1,
       const float* __restrict__ Wih2, const float* __restrict__ Whh2,
       const float* __restrict__ bih2, const float* __restrict__ bhh2,
       const float* __restrict__ Wih3, const float* __restrict__ Whh3,
       const float* __restrict__ bih3, const float* __restrict__ bhh3,
       const float* __restrict__ Wlin, const float* __restrict__ blin,
       float* __restrict__ out)
{
    extern __shared__ float sm[];
    float* W  = sm;
    float* A  = sm + OFF_A;
    float* G  = sm + OFF_G;
    float* BS = sm + OFF_BS;
    float* WL = sm + OFF_WL;

    const int tid = threadIdx.x;
    unsigned rank; asm("mov.u32 %0, %%cluster_ctarank;" : "=r"(rank));
    const int b0 = (blockIdx.x >> 3) * 16;

    // ---- one-time loads ----
    const float* WihA[3] = {Wih1, Wih2, Wih3};
    const float* WhhA[3] = {Whh1, Whh2, Whh3};
    const float* bihA[3] = {bih1, bih2, bih3};
    const float* bhhA[3] = {bhh1, bhh2, bhh3};
    const int KihA[3] = {1, 129, 257};
    const int KA[3]   = {K1, K2, K3};
    const int WO[3]   = {WOFF1, WOFF2, WOFF3};
    for (int L = 0; L < 3; L++) {
        int Kih = KihA[L], K = KA[L];
        float* Wl = W + WO[L];
        for (int i = tid; i < 64*K; i += 256) {
            int l = i & 63, k = i >> 6;
            int grow = ((l >> 4) << 7) + ((int)rank << 4) + (l & 15);
            Wl[k*64 + l] = (k < Kih) ? WihA[L][grow*Kih + k]
                                     : WhhA[L][grow*128 + (k - Kih)];
        }
        if (tid < 64) {
            int grow = ((tid >> 4) << 7) + ((int)rank << 4) + (tid & 15);
            BS[L*64 + tid] = bihA[L][grow] + bhhA[L][grow];
        }
    }
    for (int i = tid; i < 385; i += 256) WL[i] = Wlin[i];
    if (tid == 0) WL[385] = blin[0];
    for (int i = tid; i < 385*16; i += 256) A[i] = 0.f;
    __syncthreads();

    const int l  = tid & 63;       // matvec row
    const int bq = tid >> 6;       // matvec batch quad
    const int ej = tid >> 4;       // epilogue h-index
    const int eb = tid & 15;       // epilogue batch
    const unsigned sbase = (unsigned)__cvta_generic_to_shared(sm);
    float creg[3] = {0.f, 0.f, 0.f};
    float xn = (tid < 16) ? x[(b0 + tid) * 1024] : 0.f;

    for (int t = 0; t < 1056; t++) {
        if (t < 1024 && tid < 16) A[tid] = xn;     // teacher-forced input
        __syncthreads();
        if (t + 1 < 1024 && tid < 16) xn = x[(b0 + tid)*1024 + t + 1];  // prefetch

        #pragma unroll
        for (int L = 0; L < 3; L++) {
            matvec(W + WO[L], KA[L], A, G, l, bq);
            cluster_sync_();   // all A-reads done cluster-wide; G visible CTA-wide

            float gi = G[ej*16 + eb]          + BS[L*64 + ej];
            float gf = G[(16 + ej)*16 + eb]   + BS[L*64 + 16 + ej];
            float gg = G[(32 + ej)*16 + eb]   + BS[L*64 + 32 + ej];
            float go = G[(48 + ej)*16 + eb]   + BS[L*64 + 48 + ej];
            float c = sigf(gf)*creg[L] + sigf(gi)*thf(gg);
            creg[L] = c;
            float h = sigf(go)*thf(c);
            int slot = 1 + 128*L + (int)rank*16 + ej;
            unsigned addr = sbase + (unsigned)(OFF_A + slot*16 + eb)*4u;
            #pragma unroll
            for (unsigned r = 0; r < 8; r++) stc(addr, r, h);
            cluster_sync_();   // h visible in every CTA
        }

        if (rank == 0) {       // linear head: warp w -> batches 2w, 2w+1
            int w = tid >> 5, lane = tid & 31;
            #pragma unroll
            for (int bb = 0; bb < 2; bb++) {
                int b = 2*w + bb;
                float s = 0.f;
                for (int slot = lane; slot < 385; slot += 32)
                    s += A[slot*16 + b] * WL[slot];
                #pragma unroll
                for (int off = 16; off; off >>= 1)
                    s += __shfl_xor_sync(0xffffffffu, s, off);
                if (lane == 0) {
                    float o = s + WL[385];
                    out[(b0 + b)*1056 + t] = o;
                    if (t >= 1023) {   // autoregressive feedback as next input
                        unsigned a0 = sbase + (unsigned)(OFF_A + b)*4u;
                        #pragma unroll
                        for (unsigned r = 0; r < 8; r++) stc(a0, r, o);
                    }
                }
            }
        }
        cluster_sync_();       // out/feedback done before next step touches A[0]
    }
}

extern "C" void kernel_launch(void* const* d_in, const int* in_sizes, int n_in,
                              void* d_out, int out_size) {
    cudaFuncSetAttribute(lstm_k, cudaFuncAttributeMaxDynamicSharedMemorySize, SMEM_BYTES);
    lstm_k<<<128, 256, SMEM_BYTES>>>(
        (const float*)d_in[0],
        (const float*)d_in[1], (const float*)d_in[2],
        (const float*)d_in[3], (const float*)d_in[4],
        (const float*)d_in[5], (const float*)d_in[6],
        (const float*)d_in[7], (const float*)d_in[8],
        (const float*)d_in[9], (const float*)d_in[10],
        (const float*)d_in[11], (const float*)d_in[12],
        (const float*)d_in[13], (const float*)d_in[14],
        (float*)d_out);
}